// round 13
// baseline (speedup 1.0000x reference)
#include <cuda_runtime.h>
#include <cuda_fp16.h>
#include <cstdint>

// ---------------- scratch (no allocations allowed) ----------------
__device__ float    g_qkv[(size_t)8 * 768 * 4096];   // fp32
__device__ float    g_agg[(size_t)8 * 768 * 4096];   // fp32
__device__ float    g_kv[8 * 64 * 72];
// packed half2 (k even, k odd) split operands
__device__ uint32_t g_xb[(size_t)8 * 128 * 4096];    // x big   [b][kp][px]
__device__ uint32_t g_xs[(size_t)8 * 128 * 4096];    // x small
__device__ uint32_t g_attb[(size_t)8 * 256 * 4096];  // att big [b][kp][px]
__device__ uint32_t g_atts[(size_t)8 * 256 * 4096];
__device__ uint32_t g_wqb[768 * 128];                // w_qkv big  [m][kp]
__device__ uint32_t g_wqs[768 * 128];
__device__ uint32_t g_wpb[256 * 256];                // w_proj big [m][kp]
__device__ uint32_t g_wps[256 * 256];

#define HW 4096
#define NB 8
#define A_SCALE 128.0f
#define B_SCALE 16.0f
#define INV_SC  (1.0f / (A_SCALE * B_SCALE))   // 2^-11

// split scaled pair into packed fp16 big + small
__device__ __forceinline__ void splith(float x, float y, float sc,
                                       uint32_t& pb, uint32_t& ps) {
    float xs = x * sc, ys = y * sc;
    __half hx = __float2half_rn(xs), hy = __float2half_rn(ys);
    float rx = xs - __half2float(hx), ry = ys - __half2float(hy);
    __half sx = __float2half_rn(rx), sy = __float2half_rn(ry);
    __half2 vb = __halves2half2(hx, hy);
    __half2 vs = __halves2half2(sx, sy);
    pb = *reinterpret_cast<uint32_t*>(&vb);
    ps = *reinterpret_cast<uint32_t*>(&vs);
}

#define MMA_F16(C, Ar, Br)                                               \
    asm volatile(                                                        \
        "mma.sync.aligned.m16n8k16.row.col.f32.f16.f16.f32 "             \
        "{%0,%1,%2,%3}, {%4,%5,%6,%7}, {%8,%9}, {%0,%1,%2,%3};"          \
        : "+f"((C)[0]), "+f"((C)[1]), "+f"((C)[2]), "+f"((C)[3])         \
        : "r"((Ar)[0]), "r"((Ar)[1]), "r"((Ar)[2]), "r"((Ar)[3]),        \
          "r"((Br)[0]), "r"((Br)[1]))

#define CP_ASYNC16(smem_addr, gptr)                                      \
    asm volatile("cp.async.cg.shared.global [%0], [%1], 16;"             \
                 :: "r"(smem_addr), "l"(gptr) : "memory")

// ---------------- weight split kernel (tiny) ----------------
__global__ void split_w_kernel(const float* __restrict__ wq,
                               const float* __restrict__ wp)
{
    int idx = blockIdx.x * 256 + threadIdx.x;
    if (idx < 768 * 128) {
        int m = idx >> 7, kp = idx & 127;
        float2 v = *reinterpret_cast<const float2*>(&wq[m * 256 + 2 * kp]);
        splith(v.x, v.y, A_SCALE, g_wqb[idx], g_wqs[idx]);
    } else {
        int j = idx - 768 * 128;
        if (j < 256 * 256) {
            int m = j >> 8, kp = j & 255;
            float2 v = *reinterpret_cast<const float2*>(&wp[m * 512 + 2 * kp]);
            splith(v.x, v.y, A_SCALE, g_wpb[j], g_wps[j]);
        }
    }
}

// ---------------- x split kernel ----------------
__global__ __launch_bounds__(256)
void split_x_kernel(const float* __restrict__ x)
{
    int idx = blockIdx.x * 256 + threadIdx.x;    // [b][kp][p]
    int p = idx & 4095;
    int rest = idx >> 12;
    int kp = rest & 127;
    int b = rest >> 7;
    const float* xp = x + ((size_t)b * 256 + 2 * kp) * HW + p;
    splith(xp[0], xp[HW], B_SCALE, g_xb[idx], g_xs[idx]);
}

// ---------------- fp16 split tensor-core GEMM, cp.async double-buffered ----------------
#define ST_AS 10240
#define ST_BB 20480
#define ST_BS 29184
#define STAGE 37888
#define GEMM_SMEM (2 * STAGE)   // 75776

__global__ __launch_bounds__(256, 2)
void gemm_kernel(const uint32_t* __restrict__ Ab, const uint32_t* __restrict__ As,
                 const uint32_t* __restrict__ Bb, const uint32_t* __restrict__ Bs,
                 float* __restrict__ Cdst, int Kp,
                 const float* __restrict__ bn_gamma, const float* __restrict__ bn_beta,
                 const float* __restrict__ bn_mean,  const float* __restrict__ bn_var)
{
    extern __shared__ __align__(16) char smem[];
    uint32_t sbase;
    asm("{ .reg .u64 t; cvta.to.shared.u64 t, %1; cvt.u32.u64 %0, t; }"
        : "=r"(sbase) : "l"(smem));

    const int tid  = threadIdx.x;
    const int lane = tid & 31;
    const int warp = tid >> 5;
    const int warpM = (warp >> 2) * 64;
    const int warpN = (warp & 3) * 32;
    const int lq = lane >> 2;
    const int lr = lane & 3;

    const int b  = blockIdx.z;
    const int m0 = blockIdx.y * 128;
    const int n0 = blockIdx.x * 128;
    const int M  = gridDim.y * 128;
    const uint32_t* Bpb = Bb + (size_t)b * Kp * HW;
    const uint32_t* Bps = Bs + (size_t)b * Kp * HW;
    float* Cp = Cdst + (size_t)b * M * HW;

    const int arow = tid >> 2, aq = (tid & 3) * 4;
    const int arow2 = (tid + 256) >> 2, aq2 = ((tid + 256) & 3) * 4;
    const int brow = tid >> 5, bcg = (tid & 31) * 4;
    const int brow2 = (tid + 256) >> 5, bcg2 = ((tid + 256) & 31) * 4;

    float c[4][4][4];
#pragma unroll
    for (int mi = 0; mi < 4; mi++)
#pragma unroll
        for (int ni = 0; ni < 4; ni++)
#pragma unroll
            for (int r = 0; r < 4; r++) c[mi][ni][r] = 0.f;

    const int nch = Kp >> 4;

    auto load_stage = [&](int st, int ck) {
        uint32_t sb = sbase + st * STAGE;
        const uint32_t* a0 = Ab + (size_t)(m0 + arow) * Kp + ck * 16 + aq;
        const uint32_t* a1 = Ab + (size_t)(m0 + arow2) * Kp + ck * 16 + aq2;
        const uint32_t* a2 = As + (size_t)(m0 + arow) * Kp + ck * 16 + aq;
        const uint32_t* a3 = As + (size_t)(m0 + arow2) * Kp + ck * 16 + aq2;
        CP_ASYNC16(sb + (arow * 20 + aq) * 4, a0);
        CP_ASYNC16(sb + (arow2 * 20 + aq2) * 4, a1);
        CP_ASYNC16(sb + ST_AS + (arow * 20 + aq) * 4, a2);
        CP_ASYNC16(sb + ST_AS + (arow2 * 20 + aq2) * 4, a3);
        const uint32_t* b0 = Bpb + (size_t)(ck * 16 + brow) * HW + n0 + bcg;
        const uint32_t* b1 = Bpb + (size_t)(ck * 16 + brow2) * HW + n0 + bcg2;
        const uint32_t* b2 = Bps + (size_t)(ck * 16 + brow) * HW + n0 + bcg;
        const uint32_t* b3 = Bps + (size_t)(ck * 16 + brow2) * HW + n0 + bcg2;
        CP_ASYNC16(sb + ST_BB + (brow * 136 + bcg) * 4, b0);
        CP_ASYNC16(sb + ST_BB + (brow2 * 136 + bcg2) * 4, b1);
        CP_ASYNC16(sb + ST_BS + (brow * 136 + bcg) * 4, b2);
        CP_ASYNC16(sb + ST_BS + (brow2 * 136 + bcg2) * 4, b3);
        asm volatile("cp.async.commit_group;" ::: "memory");
    };

    load_stage(0, 0);

    for (int ck = 0; ck < nch; ++ck) {
        if (ck + 1 < nch) {
            load_stage((ck + 1) & 1, ck + 1);
            asm volatile("cp.async.wait_group 1;" ::: "memory");
        } else {
            asm volatile("cp.async.wait_group 0;" ::: "memory");
        }
        __syncthreads();

        const uint32_t* Ab_s = (const uint32_t*)(smem + (ck & 1) * STAGE);
        const uint32_t* As_s = (const uint32_t*)(smem + (ck & 1) * STAGE + ST_AS);
        const uint32_t* Bb_s = (const uint32_t*)(smem + (ck & 1) * STAGE + ST_BB);
        const uint32_t* Bs_s = (const uint32_t*)(smem + (ck & 1) * STAGE + ST_BS);

#pragma unroll
        for (int ks = 0; ks < 2; ++ks) {
            const int kb = ks * 8;
            uint32_t bbf[4][2], bsf[4][2];
#pragma unroll
            for (int ni = 0; ni < 4; ++ni) {
                int col = warpN + ni * 8 + lq;
                bbf[ni][0] = Bb_s[(kb + lr) * 136 + col];
                bbf[ni][1] = Bb_s[(kb + lr + 4) * 136 + col];
                bsf[ni][0] = Bs_s[(kb + lr) * 136 + col];
                bsf[ni][1] = Bs_s[(kb + lr + 4) * 136 + col];
            }
#pragma unroll
            for (int mi = 0; mi < 4; ++mi) {
                int r = warpM + mi * 16 + lq;
                int kc = kb + lr;
                uint32_t abf[4] = { Ab_s[r * 20 + kc], Ab_s[(r + 8) * 20 + kc],
                                    Ab_s[r * 20 + kc + 4], Ab_s[(r + 8) * 20 + kc + 4] };
                uint32_t asf[4] = { As_s[r * 20 + kc], As_s[(r + 8) * 20 + kc],
                                    As_s[r * 20 + kc + 4], As_s[(r + 8) * 20 + kc + 4] };
#pragma unroll
                for (int ni = 0; ni < 4; ++ni) {
                    MMA_F16(c[mi][ni], asf, bbf[ni]);   // small x big
                    MMA_F16(c[mi][ni], abf, bsf[ni]);   // big x small
                    MMA_F16(c[mi][ni], abf, bbf[ni]);   // big x big
                }
            }
        }
        __syncthreads();
    }

#pragma unroll
    for (int mi = 0; mi < 4; ++mi) {
        int r0 = m0 + warpM + mi * 16 + lq;
        int r1 = r0 + 8;
        float s0 = INV_SC, b0 = 0.f, s1 = INV_SC, b1 = 0.f;
        if (bn_gamma) {
            float inv0 = bn_gamma[r0] * rsqrtf(bn_var[r0] + 1e-5f);
            float inv1 = bn_gamma[r1] * rsqrtf(bn_var[r1] + 1e-5f);
            s0 = inv0 * INV_SC; b0 = bn_beta[r0] - bn_mean[r0] * inv0;
            s1 = inv1 * INV_SC; b1 = bn_beta[r1] - bn_mean[r1] * inv1;
        }
#pragma unroll
        for (int ni = 0; ni < 4; ++ni) {
            int n = n0 + warpN + ni * 8 + lr * 2;
            float2 v0, v1;
            v0.x = c[mi][ni][0] * s0 + b0;
            v0.y = c[mi][ni][1] * s0 + b0;
            v1.x = c[mi][ni][2] * s1 + b1;
            v1.y = c[mi][ni][3] * s1 + b1;
            *reinterpret_cast<float2*>(&Cp[(size_t)r0 * HW + n]) = v0;
            *reinterpret_cast<float2*>(&Cp[(size_t)r1 * HW + n]) = v1;
        }
    }
}

// ---------------- fused depthwise 5x5 + grouped pointwise 8x8 -> agg ----------------
// Register-blocked 4-row strips (R11 budget: occ 2, no reg cap squeeze)
// + division-free warp-per-channel halo loader (R12).
__global__ __launch_bounds__(256, 2)
void dwpw_kernel(const float* __restrict__ qkv,
                 const float* __restrict__ w_dw,
                 const float* __restrict__ w_pw,
                 float* __restrict__ agg)
{
    const int tile = blockIdx.x;
    const int g = blockIdx.y;
    const int b = blockIdx.z;
    const int ty0 = (tile >> 1) * 32;
    const int tx0 = (tile & 1) * 32;

    __shared__ float s_in[8][36][36];
    __shared__ float s_dw[8][25];
    __shared__ float s_pw[8][8];

    const int tid  = threadIdx.x;
    const int lane = tid & 31;
    if (tid < 200) s_dw[tid / 25][tid % 25] = w_dw[(g * 8 + tid / 25) * 25 + tid % 25];
    if (tid < 64)  s_pw[tid >> 3][tid & 7] = w_pw[g * 64 + tid];

    // ---- loader: warp wc loads channel wc's 36x36 halo slice (no divisions) ----
    {
        const int wc = tid >> 5;
        const float* src = qkv + ((size_t)b * 768 + g * 8 + wc) * HW;
        const int x1 = tx0 + lane - 2;
        const bool xv1 = (x1 >= 0) && (x1 < 64);
        const int x2 = tx0 + lane + 30;
        const bool do2 = (lane < 4);
        const bool xv2 = do2 && (x2 < 64);
#pragma unroll 6
        for (int r = 0; r < 36; ++r) {
            int y = ty0 + r - 2;
            bool yv = (y >= 0) && (y < 64);
            float v1 = (xv1 && yv) ? src[y * 64 + x1] : 0.f;
            s_in[wc][r][lane] = v1;
            if (do2) {
                float v2 = (xv2 && yv) ? src[y * 64 + x2] : 0.f;
                s_in[wc][r][lane + 32] = v2;
            }
        }
    }
    __syncthreads();

    const int px  = lane;           // column within tile
    const int py0 = (tid >> 5) * 4; // strip of 4 output rows

    float out[8][4];
#pragma unroll
    for (int o = 0; o < 8; ++o)
#pragma unroll
        for (int p = 0; p < 4; ++p) out[o][p] = 0.f;

#pragma unroll
    for (int c = 0; c < 8; ++c) {
        float w[25];
#pragma unroll
        for (int i = 0; i < 25; ++i) w[i] = s_dw[c][i];

        float acc[4] = {0.f, 0.f, 0.f, 0.f};
#pragma unroll
        for (int j = 0; j < 8; ++j) {       // input rows py0-2 .. py0+5 (smem rows py0+j)
            float win[5];
#pragma unroll
            for (int dx = 0; dx < 5; ++dx) win[dx] = s_in[c][py0 + j][px + dx];
#pragma unroll
            for (int o = 0; o < 4; ++o) {
                const int dy = j - o;       // compile-time per (j,o)
                if (dy >= 0 && dy <= 4) {
#pragma unroll
                    for (int dx = 0; dx < 5; ++dx)
                        acc[o] = fmaf(win[dx], w[dy * 5 + dx], acc[o]);
                }
            }
        }
#pragma unroll
        for (int o = 0; o < 8; ++o) {
            float pw = s_pw[o][c];
#pragma unroll
            for (int p = 0; p < 4; ++p) out[o][p] = fmaf(pw, acc[p], out[o][p]);
        }
    }

    float* obase = agg + ((size_t)b * 768 + g * 8) * HW + (ty0 + py0) * 64 + tx0 + px;
#pragma unroll
    for (int o = 0; o < 8; ++o) {
#pragma unroll
        for (int p = 0; p < 4; ++p)
            obase[(size_t)o * HW + p * 64] = out[o][p];
    }
}

// ---------------- kv = sum_p relu(k)_d * [v_e | 1]  per (b, head) ----------------
__global__ __launch_bounds__(256, 4)
void kv_kernel(const float* __restrict__ qkv,
               const float* __restrict__ agg,
               float* __restrict__ kvout)
{
    const int h = blockIdx.x, b = blockIdx.y;
    const float* src = (h < 32) ? qkv : agg;
    const int cbase = (h & 31) * 24;
    const float* kp = src + ((size_t)b * 768 + cbase + 8) * HW;
    const float* vp = src + ((size_t)b * 768 + cbase + 16) * HW;

    float acc[8][9];
#pragma unroll
    for (int d = 0; d < 8; d++)
#pragma unroll
        for (int e = 0; e < 9; e++) acc[d][e] = 0.f;

    for (int p = threadIdx.x; p < HW; p += 256) {
        float kk[8], vv[8];
#pragma unroll
        for (int d = 0; d < 8; d++) kk[d] = fmaxf(kp[(size_t)d * HW + p], 0.f);
#pragma unroll
        for (int e = 0; e < 8; e++) vv[e] = vp[(size_t)e * HW + p];
#pragma unroll
        for (int d = 0; d < 8; d++) {
#pragma unroll
            for (int e = 0; e < 8; e++) acc[d][e] = fmaf(kk[d], vv[e], acc[d][e]);
            acc[d][8] += kk[d];
        }
    }

    __shared__ float red[8][72];
    const int lane = threadIdx.x & 31, w = threadIdx.x >> 5;
#pragma unroll
    for (int i = 0; i < 72; ++i) {
        float v = acc[i / 9][i % 9];
#pragma unroll
        for (int off = 16; off; off >>= 1) v += __shfl_down_sync(0xffffffffu, v, off);
        if (lane == 0) red[w][i] = v;
    }
    __syncthreads();
    if (threadIdx.x < 72) {
        float s = 0.f;
#pragma unroll
        for (int w2 = 0; w2 < 8; ++w2) s += red[w2][threadIdx.x];
        kvout[((size_t)b * 64 + h) * 72 + threadIdx.x] = s;
    }
}

// ---------------- apply + fused att split ----------------
__global__ __launch_bounds__(256, 4)
void apply_kernel(const float* __restrict__ qkv,
                  const float* __restrict__ agg,
                  const float* __restrict__ kvin,
                  uint32_t* __restrict__ attb,
                  uint32_t* __restrict__ atts)
{
    const int h = blockIdx.y, b = blockIdx.z;
    __shared__ float kv[8][9];
    if (threadIdx.x < 72)
        kv[threadIdx.x / 9][threadIdx.x % 9] = kvin[((size_t)b * 64 + h) * 72 + threadIdx.x];
    __syncthreads();

    const float* src = (h < 32) ? qkv : agg;
    const int cbase = (h & 31) * 24;
    const float* qp = src + ((size_t)b * 768 + cbase) * HW;
    const int p = blockIdx.x * 256 + threadIdx.x;

    float q[8];
#pragma unroll
    for (int d = 0; d < 8; d++) q[d] = fmaxf(qp[(size_t)d * HW + p], 0.f);

    float den = 0.f;
#pragma unroll
    for (int d = 0; d < 8; d++) den = fmaf(q[d], kv[d][8], den);
    const float inv = 1.f / (den + 1e-15f);

    float o[8];
#pragma unroll
    for (int n = 0; n < 8; ++n) {
        float s = 0.f;
#pragma unroll
        for (int d = 0; d < 8; d++) s = fmaf(q[d], kv[d][n], s);
        o[n] = s * inv;
    }

    uint32_t* wb = attb + ((size_t)b * 256 + h * 4) * HW + p;
    uint32_t* ws = atts + ((size_t)b * 256 + h * 4) * HW + p;
#pragma unroll
    for (int j = 0; j < 4; ++j) {
        uint32_t ub, us;
        splith(o[2 * j], o[2 * j + 1], B_SCALE, ub, us);
        wb[(size_t)j * HW] = ub;
        ws[(size_t)j * HW] = us;
    }
}

// ---------------- launch ----------------
extern "C" void kernel_launch(void* const* d_in, const int* in_sizes, int n_in,
                              void* d_out, int out_size)
{
    const float* x        = (const float*)d_in[0];
    const float* w_qkv    = (const float*)d_in[1];
    const float* w_dw     = (const float*)d_in[2];
    const float* w_pw     = (const float*)d_in[3];
    const float* w_proj   = (const float*)d_in[4];
    const float* bn_gamma = (const float*)d_in[5];
    const float* bn_beta  = (const float*)d_in[6];
    const float* bn_mean  = (const float*)d_in[7];
    const float* bn_var   = (const float*)d_in[8];
    float* out = (float*)d_out;

    float *qkv, *agg, *kv;
    uint32_t *xb, *xs, *attb, *atts, *wqb, *wqs, *wpb, *wps;
    cudaGetSymbolAddress((void**)&qkv,  g_qkv);
    cudaGetSymbolAddress((void**)&agg,  g_agg);
    cudaGetSymbolAddress((void**)&kv,   g_kv);
    cudaGetSymbolAddress((void**)&xb,   g_xb);
    cudaGetSymbolAddress((void**)&xs,   g_xs);
    cudaGetSymbolAddress((void**)&attb, g_attb);
    cudaGetSymbolAddress((void**)&atts, g_atts);
    cudaGetSymbolAddress((void**)&wqb,  g_wqb);
    cudaGetSymbolAddress((void**)&wqs,  g_wqs);
    cudaGetSymbolAddress((void**)&wpb,  g_wpb);
    cudaGetSymbolAddress((void**)&wps,  g_wps);

    cudaFuncSetAttribute(gemm_kernel,
                         cudaFuncAttributeMaxDynamicSharedMemorySize, GEMM_SMEM);

    // 0) pre-split weights and x into fp16 big/small (packed pairs)
    split_w_kernel<<<(768 * 128 + 256 * 256 + 255) / 256, 256>>>(w_qkv, w_proj);
    split_x_kernel<<<(8 * 128 * 4096) / 256, 256>>>(x);

    // 1) qkv = w_qkv @ x   (M=768, Kp=128)
    gemm_kernel<<<dim3(HW / 128, 6, NB), 256, GEMM_SMEM>>>(
        wqb, wqs, xb, xs, qkv, 128, nullptr, nullptr, nullptr, nullptr);

    // 2) agg = grouped-pw(depthwise5x5(qkv))
    dwpw_kernel<<<dim3(4, 96, NB), 256>>>(qkv, w_dw, w_pw, agg);

    // 3) kv reduction per (b, head)
    kv_kernel<<<dim3(64, NB), 256>>>(qkv, agg, kv);

    // 4) apply -> att (fp16 split, fused)
    apply_kernel<<<dim3(HW / 256, 64, NB), 256>>>(qkv, agg, kv, attb, atts);

    // 5) out = BN(w_proj @ att)   (M=256, Kp=256)
    gemm_kernel<<<dim3(HW / 128, 2, NB), 256, GEMM_SMEM>>>(
        wpb, wps, attb, atts, out, 256, bn_gamma, bn_beta, bn_mean, bn_var);
}

// round 14
// speedup vs baseline: 1.3041x; 1.3041x over previous
#include <cuda_runtime.h>
#include <cuda_fp16.h>
#include <cstdint>

// ---------------- scratch (no allocations allowed) ----------------
__device__ float    g_qkv[(size_t)8 * 768 * 4096];   // fp32
__device__ float    g_agg[(size_t)8 * 768 * 4096];   // fp32
__device__ float    g_kv[8 * 64 * 72];
// packed half2 (k even, k odd) split operands
__device__ uint32_t g_xb[(size_t)8 * 128 * 4096];    // x big   [b][kp][px]
__device__ uint32_t g_xs[(size_t)8 * 128 * 4096];    // x small
__device__ uint32_t g_attb[(size_t)8 * 256 * 4096];  // att big [b][kp][px]
__device__ uint32_t g_atts[(size_t)8 * 256 * 4096];
__device__ uint32_t g_wqb[768 * 128];                // w_qkv big  [m][kp]
__device__ uint32_t g_wqs[768 * 128];
__device__ uint32_t g_wpb[256 * 256];                // w_proj big [m][kp]
__device__ uint32_t g_wps[256 * 256];

#define HW 4096
#define NB 8
#define A_SCALE 128.0f
#define B_SCALE 16.0f
#define INV_SC  (1.0f / (A_SCALE * B_SCALE))   // 2^-11

// split scaled pair into packed fp16 big + small
__device__ __forceinline__ void splith(float x, float y, float sc,
                                       uint32_t& pb, uint32_t& ps) {
    float xs = x * sc, ys = y * sc;
    __half hx = __float2half_rn(xs), hy = __float2half_rn(ys);
    float rx = xs - __half2float(hx), ry = ys - __half2float(hy);
    __half sx = __float2half_rn(rx), sy = __float2half_rn(ry);
    __half2 vb = __halves2half2(hx, hy);
    __half2 vs = __halves2half2(sx, sy);
    pb = *reinterpret_cast<uint32_t*>(&vb);
    ps = *reinterpret_cast<uint32_t*>(&vs);
}

#define MMA_F16(C, Ar, Br)                                               \
    asm volatile(                                                        \
        "mma.sync.aligned.m16n8k16.row.col.f32.f16.f16.f32 "             \
        "{%0,%1,%2,%3}, {%4,%5,%6,%7}, {%8,%9}, {%0,%1,%2,%3};"          \
        : "+f"((C)[0]), "+f"((C)[1]), "+f"((C)[2]), "+f"((C)[3])         \
        : "r"((Ar)[0]), "r"((Ar)[1]), "r"((Ar)[2]), "r"((Ar)[3]),        \
          "r"((Br)[0]), "r"((Br)[1]))

#define CP_ASYNC16(smem_addr, gptr)                                      \
    asm volatile("cp.async.cg.shared.global [%0], [%1], 16;"             \
                 :: "r"(smem_addr), "l"(gptr) : "memory")

// ---------------- weight split kernel (tiny) ----------------
__global__ void split_w_kernel(const float* __restrict__ wq,
                               const float* __restrict__ wp)
{
    int idx = blockIdx.x * 256 + threadIdx.x;
    if (idx < 768 * 128) {
        int m = idx >> 7, kp = idx & 127;
        float2 v = *reinterpret_cast<const float2*>(&wq[m * 256 + 2 * kp]);
        splith(v.x, v.y, A_SCALE, g_wqb[idx], g_wqs[idx]);
    } else {
        int j = idx - 768 * 128;
        if (j < 256 * 256) {
            int m = j >> 8, kp = j & 255;
            float2 v = *reinterpret_cast<const float2*>(&wp[m * 512 + 2 * kp]);
            splith(v.x, v.y, A_SCALE, g_wpb[j], g_wps[j]);
        }
    }
}

// ---------------- x split kernel ----------------
__global__ __launch_bounds__(256)
void split_x_kernel(const float* __restrict__ x)
{
    int idx = blockIdx.x * 256 + threadIdx.x;    // [b][kp][p]
    int p = idx & 4095;
    int rest = idx >> 12;
    int kp = rest & 127;
    int b = rest >> 7;
    const float* xp = x + ((size_t)b * 256 + 2 * kp) * HW + p;
    splith(xp[0], xp[HW], B_SCALE, g_xb[idx], g_xs[idx]);
}

// ---------------- fp16 split tensor-core GEMM, cp.async 3-stage pipeline ----------------
#define ST_AS 10240
#define ST_BB 20480
#define ST_BS 29184
#define STAGE 37888
#define GEMM_SMEM (3 * STAGE)   // 113664

__global__ __launch_bounds__(256, 2)
void gemm_kernel(const uint32_t* __restrict__ Ab, const uint32_t* __restrict__ As,
                 const uint32_t* __restrict__ Bb, const uint32_t* __restrict__ Bs,
                 float* __restrict__ Cdst, int Kp,
                 const float* __restrict__ bn_gamma, const float* __restrict__ bn_beta,
                 const float* __restrict__ bn_mean,  const float* __restrict__ bn_var)
{
    extern __shared__ __align__(16) char smem[];
    uint32_t sbase;
    asm("{ .reg .u64 t; cvta.to.shared.u64 t, %1; cvt.u32.u64 %0, t; }"
        : "=r"(sbase) : "l"(smem));

    const int tid  = threadIdx.x;
    const int lane = tid & 31;
    const int warp = tid >> 5;
    const int warpM = (warp >> 2) * 64;
    const int warpN = (warp & 3) * 32;
    const int lq = lane >> 2;
    const int lr = lane & 3;

    const int b  = blockIdx.z;
    const int m0 = blockIdx.y * 128;
    const int n0 = blockIdx.x * 128;
    const int M  = gridDim.y * 128;
    const uint32_t* Bpb = Bb + (size_t)b * Kp * HW;
    const uint32_t* Bps = Bs + (size_t)b * Kp * HW;
    float* Cp = Cdst + (size_t)b * M * HW;

    const int arow = tid >> 2, aq = (tid & 3) * 4;
    const int arow2 = (tid + 256) >> 2, aq2 = ((tid + 256) & 3) * 4;
    const int brow = tid >> 5, bcg = (tid & 31) * 4;
    const int brow2 = (tid + 256) >> 5, bcg2 = ((tid + 256) & 31) * 4;

    float c[4][4][4];
#pragma unroll
    for (int mi = 0; mi < 4; mi++)
#pragma unroll
        for (int ni = 0; ni < 4; ni++)
#pragma unroll
            for (int r = 0; r < 4; r++) c[mi][ni][r] = 0.f;

    const int nch = Kp >> 4;

    auto load_stage = [&](int st, int ck) {
        uint32_t sb = sbase + st * STAGE;
        const uint32_t* a0 = Ab + (size_t)(m0 + arow) * Kp + ck * 16 + aq;
        const uint32_t* a1 = Ab + (size_t)(m0 + arow2) * Kp + ck * 16 + aq2;
        const uint32_t* a2 = As + (size_t)(m0 + arow) * Kp + ck * 16 + aq;
        const uint32_t* a3 = As + (size_t)(m0 + arow2) * Kp + ck * 16 + aq2;
        CP_ASYNC16(sb + (arow * 20 + aq) * 4, a0);
        CP_ASYNC16(sb + (arow2 * 20 + aq2) * 4, a1);
        CP_ASYNC16(sb + ST_AS + (arow * 20 + aq) * 4, a2);
        CP_ASYNC16(sb + ST_AS + (arow2 * 20 + aq2) * 4, a3);
        const uint32_t* b0 = Bpb + (size_t)(ck * 16 + brow) * HW + n0 + bcg;
        const uint32_t* b1 = Bpb + (size_t)(ck * 16 + brow2) * HW + n0 + bcg2;
        const uint32_t* b2 = Bps + (size_t)(ck * 16 + brow) * HW + n0 + bcg;
        const uint32_t* b3 = Bps + (size_t)(ck * 16 + brow2) * HW + n0 + bcg2;
        CP_ASYNC16(sb + ST_BB + (brow * 136 + bcg) * 4, b0);
        CP_ASYNC16(sb + ST_BB + (brow2 * 136 + bcg2) * 4, b1);
        CP_ASYNC16(sb + ST_BS + (brow * 136 + bcg) * 4, b2);
        CP_ASYNC16(sb + ST_BS + (brow2 * 136 + bcg2) * 4, b3);
        asm volatile("cp.async.commit_group;" ::: "memory");
    };

    // prologue: stages 0 and 1 in flight
    load_stage(0, 0);
    load_stage(1, 1);

    int st = 0;                      // stage of chunk ck
    for (int ck = 0; ck < nch; ++ck) {
        if (ck + 1 < nch) {
            asm volatile("cp.async.wait_group 1;" ::: "memory");
        } else {
            asm volatile("cp.async.wait_group 0;" ::: "memory");
        }
        __syncthreads();
        // issue prefetch for ck+2 into stage (st+2)%3; safe: barrier above
        // guarantees every warp finished computing on that buffer (chunk ck-1).
        if (ck + 2 < nch) {
            int st2 = st + 2 >= 3 ? st - 1 : st + 2;
            load_stage(st2, ck + 2);
        }

        const uint32_t* Ab_s = (const uint32_t*)(smem + st * STAGE);
        const uint32_t* As_s = (const uint32_t*)(smem + st * STAGE + ST_AS);
        const uint32_t* Bb_s = (const uint32_t*)(smem + st * STAGE + ST_BB);
        const uint32_t* Bs_s = (const uint32_t*)(smem + st * STAGE + ST_BS);

#pragma unroll
        for (int ks = 0; ks < 2; ++ks) {
            const int kb = ks * 8;
            uint32_t bbf[4][2], bsf[4][2];
#pragma unroll
            for (int ni = 0; ni < 4; ++ni) {
                int col = warpN + ni * 8 + lq;
                bbf[ni][0] = Bb_s[(kb + lr) * 136 + col];
                bbf[ni][1] = Bb_s[(kb + lr + 4) * 136 + col];
                bsf[ni][0] = Bs_s[(kb + lr) * 136 + col];
                bsf[ni][1] = Bs_s[(kb + lr + 4) * 136 + col];
            }
#pragma unroll
            for (int mi = 0; mi < 4; ++mi) {
                int r = warpM + mi * 16 + lq;
                int kc = kb + lr;
                uint32_t abf[4] = { Ab_s[r * 20 + kc], Ab_s[(r + 8) * 20 + kc],
                                    Ab_s[r * 20 + kc + 4], Ab_s[(r + 8) * 20 + kc + 4] };
                uint32_t asf[4] = { As_s[r * 20 + kc], As_s[(r + 8) * 20 + kc],
                                    As_s[r * 20 + kc + 4], As_s[(r + 8) * 20 + kc + 4] };
#pragma unroll
                for (int ni = 0; ni < 4; ++ni) {
                    MMA_F16(c[mi][ni], asf, bbf[ni]);   // small x big
                    MMA_F16(c[mi][ni], abf, bsf[ni]);   // big x small
                    MMA_F16(c[mi][ni], abf, bbf[ni]);   // big x big
                }
            }
        }
        st = (st + 1 == 3) ? 0 : st + 1;
    }

#pragma unroll
    for (int mi = 0; mi < 4; ++mi) {
        int r0 = m0 + warpM + mi * 16 + lq;
        int r1 = r0 + 8;
        float s0 = INV_SC, b0 = 0.f, s1 = INV_SC, b1 = 0.f;
        if (bn_gamma) {
            float inv0 = bn_gamma[r0] * rsqrtf(bn_var[r0] + 1e-5f);
            float inv1 = bn_gamma[r1] * rsqrtf(bn_var[r1] + 1e-5f);
            s0 = inv0 * INV_SC; b0 = bn_beta[r0] - bn_mean[r0] * inv0;
            s1 = inv1 * INV_SC; b1 = bn_beta[r1] - bn_mean[r1] * inv1;
        }
#pragma unroll
        for (int ni = 0; ni < 4; ++ni) {
            int n = n0 + warpN + ni * 8 + lr * 2;
            float2 v0, v1;
            v0.x = c[mi][ni][0] * s0 + b0;
            v0.y = c[mi][ni][1] * s0 + b0;
            v1.x = c[mi][ni][2] * s1 + b1;
            v1.y = c[mi][ni][3] * s1 + b1;
            *reinterpret_cast<float2*>(&Cp[(size_t)r0 * HW + n]) = v0;
            *reinterpret_cast<float2*>(&Cp[(size_t)r1 * HW + n]) = v1;
        }
    }
}

// ---------------- fused depthwise 5x5 + grouped pointwise 8x8 -> agg ----------------
// EXACT R11 version (measured 134us): register-blocked 4-row strips,
// strided grid loader. Do not perturb — ptxas scheduling is fragile here.
__global__ __launch_bounds__(256, 2)
void dwpw_kernel(const float* __restrict__ qkv,
                 const float* __restrict__ w_dw,
                 const float* __restrict__ w_pw,
                 float* __restrict__ agg)
{
    const int tile = blockIdx.x;
    const int g = blockIdx.y;
    const int b = blockIdx.z;
    const int ty0 = (tile >> 1) * 32;
    const int tx0 = (tile & 1) * 32;

    __shared__ float s_in[8][36][36];
    __shared__ float s_dw[8][25];
    __shared__ float s_pw[8][8];

    const int tid = threadIdx.x;
    if (tid < 200) s_dw[tid / 25][tid % 25] = w_dw[(g * 8 + tid / 25) * 25 + tid % 25];
    if (tid < 64)  s_pw[tid >> 3][tid & 7] = w_pw[g * 64 + tid];

    const float* base = qkv + ((size_t)b * 768 + g * 8) * HW;
    for (int idx = tid; idx < 8 * 36 * 36; idx += 256) {
        int c = idx / 1296;
        int rem = idx - c * 1296;
        int r = rem / 36;
        int col = rem - r * 36;
        int y = ty0 + r - 2, x = tx0 + col - 2;
        float v = 0.f;
        if (y >= 0 && y < 64 && x >= 0 && x < 64) v = base[(size_t)c * HW + y * 64 + x];
        s_in[c][r][col] = v;
    }
    __syncthreads();

    const int px  = tid & 31;       // column within tile
    const int py0 = (tid >> 5) * 4; // strip of 4 output rows

    float out[8][4];
#pragma unroll
    for (int o = 0; o < 8; ++o)
#pragma unroll
        for (int p = 0; p < 4; ++p) out[o][p] = 0.f;

#pragma unroll
    for (int c = 0; c < 8; ++c) {
        float w[25];
#pragma unroll
        for (int i = 0; i < 25; ++i) w[i] = s_dw[c][i];

        float acc[4] = {0.f, 0.f, 0.f, 0.f};
#pragma unroll
        for (int j = 0; j < 8; ++j) {       // input rows py0-2 .. py0+5 (smem rows py0+j)
            float win[5];
#pragma unroll
            for (int dx = 0; dx < 5; ++dx) win[dx] = s_in[c][py0 + j][px + dx];
#pragma unroll
            for (int o = 0; o < 4; ++o) {
                const int dy = j - o;       // compile-time per (j,o)
                if (dy >= 0 && dy <= 4) {
#pragma unroll
                    for (int dx = 0; dx < 5; ++dx)
                        acc[o] = fmaf(win[dx], w[dy * 5 + dx], acc[o]);
                }
            }
        }
#pragma unroll
        for (int o = 0; o < 8; ++o) {
            float pw = s_pw[o][c];
#pragma unroll
            for (int p = 0; p < 4; ++p) out[o][p] = fmaf(pw, acc[p], out[o][p]);
        }
    }

    float* obase = agg + ((size_t)b * 768 + g * 8) * HW;
#pragma unroll
    for (int o = 0; o < 8; ++o) {
#pragma unroll
        for (int p = 0; p < 4; ++p) {
            int off = (ty0 + py0 + p) * 64 + (tx0 + px);
            obase[(size_t)o * HW + off] = out[o][p];
        }
    }
}

// ---------------- kv = sum_p relu(k)_d * [v_e | 1]  per (b, head) ----------------
__global__ __launch_bounds__(256, 4)
void kv_kernel(const float* __restrict__ qkv,
               const float* __restrict__ agg,
               float* __restrict__ kvout)
{
    const int h = blockIdx.x, b = blockIdx.y;
    const float* src = (h < 32) ? qkv : agg;
    const int cbase = (h & 31) * 24;
    const float* kp = src + ((size_t)b * 768 + cbase + 8) * HW;
    const float* vp = src + ((size_t)b * 768 + cbase + 16) * HW;

    float acc[8][9];
#pragma unroll
    for (int d = 0; d < 8; d++)
#pragma unroll
        for (int e = 0; e < 9; e++) acc[d][e] = 0.f;

    for (int p = threadIdx.x; p < HW; p += 256) {
        float kk[8], vv[8];
#pragma unroll
        for (int d = 0; d < 8; d++) kk[d] = fmaxf(kp[(size_t)d * HW + p], 0.f);
#pragma unroll
        for (int e = 0; e < 8; e++) vv[e] = vp[(size_t)e * HW + p];
#pragma unroll
        for (int d = 0; d < 8; d++) {
#pragma unroll
            for (int e = 0; e < 8; e++) acc[d][e] = fmaf(kk[d], vv[e], acc[d][e]);
            acc[d][8] += kk[d];
        }
    }

    __shared__ float red[8][72];
    const int lane = threadIdx.x & 31, w = threadIdx.x >> 5;
#pragma unroll
    for (int i = 0; i < 72; ++i) {
        float v = acc[i / 9][i % 9];
#pragma unroll
        for (int off = 16; off; off >>= 1) v += __shfl_down_sync(0xffffffffu, v, off);
        if (lane == 0) red[w][i] = v;
    }
    __syncthreads();
    if (threadIdx.x < 72) {
        float s = 0.f;
#pragma unroll
        for (int w2 = 0; w2 < 8; ++w2) s += red[w2][threadIdx.x];
        kvout[((size_t)b * 64 + h) * 72 + threadIdx.x] = s;
    }
}

// ---------------- apply + fused att split ----------------
__global__ __launch_bounds__(256, 4)
void apply_kernel(const float* __restrict__ qkv,
                  const float* __restrict__ agg,
                  const float* __restrict__ kvin,
                  uint32_t* __restrict__ attb,
                  uint32_t* __restrict__ atts)
{
    const int h = blockIdx.y, b = blockIdx.z;
    __shared__ float kv[8][9];
    if (threadIdx.x < 72)
        kv[threadIdx.x / 9][threadIdx.x % 9] = kvin[((size_t)b * 64 + h) * 72 + threadIdx.x];
    __syncthreads();

    const float* src = (h < 32) ? qkv : agg;
    const int cbase = (h & 31) * 24;
    const float* qp = src + ((size_t)b * 768 + cbase) * HW;
    const int p = blockIdx.x * 256 + threadIdx.x;

    float q[8];
#pragma unroll
    for (int d = 0; d < 8; d++) q[d] = fmaxf(qp[(size_t)d * HW + p], 0.f);

    float den = 0.f;
#pragma unroll
    for (int d = 0; d < 8; d++) den = fmaf(q[d], kv[d][8], den);
    const float inv = 1.f / (den + 1e-15f);

    float o[8];
#pragma unroll
    for (int n = 0; n < 8; ++n) {
        float s = 0.f;
#pragma unroll
        for (int d = 0; d < 8; d++) s = fmaf(q[d], kv[d][n], s);
        o[n] = s * inv;
    }

    uint32_t* wb = attb + ((size_t)b * 256 + h * 4) * HW + p;
    uint32_t* ws = atts + ((size_t)b * 256 + h * 4) * HW + p;
#pragma unroll
    for (int j = 0; j < 4; ++j) {
        uint32_t ub, us;
        splith(o[2 * j], o[2 * j + 1], B_SCALE, ub, us);
        wb[(size_t)j * HW] = ub;
        ws[(size_t)j * HW] = us;
    }
}

// ---------------- launch ----------------
extern "C" void kernel_launch(void* const* d_in, const int* in_sizes, int n_in,
                              void* d_out, int out_size)
{
    const float* x        = (const float*)d_in[0];
    const float* w_qkv    = (const float*)d_in[1];
    const float* w_dw     = (const float*)d_in[2];
    const float* w_pw     = (const float*)d_in[3];
    const float* w_proj   = (const float*)d_in[4];
    const float* bn_gamma = (const float*)d_in[5];
    const float* bn_beta  = (const float*)d_in[6];
    const float* bn_mean  = (const float*)d_in[7];
    const float* bn_var   = (const float*)d_in[8];
    float* out = (float*)d_out;

    float *qkv, *agg, *kv;
    uint32_t *xb, *xs, *attb, *atts, *wqb, *wqs, *wpb, *wps;
    cudaGetSymbolAddress((void**)&qkv,  g_qkv);
    cudaGetSymbolAddress((void**)&agg,  g_agg);
    cudaGetSymbolAddress((void**)&kv,   g_kv);
    cudaGetSymbolAddress((void**)&xb,   g_xb);
    cudaGetSymbolAddress((void**)&xs,   g_xs);
    cudaGetSymbolAddress((void**)&attb, g_attb);
    cudaGetSymbolAddress((void**)&atts, g_atts);
    cudaGetSymbolAddress((void**)&wqb,  g_wqb);
    cudaGetSymbolAddress((void**)&wqs,  g_wqs);
    cudaGetSymbolAddress((void**)&wpb,  g_wpb);
    cudaGetSymbolAddress((void**)&wps,  g_wps);

    cudaFuncSetAttribute(gemm_kernel,
                         cudaFuncAttributeMaxDynamicSharedMemorySize, GEMM_SMEM);

    // 0) pre-split weights and x into fp16 big/small (packed pairs)
    split_w_kernel<<<(768 * 128 + 256 * 256 + 255) / 256, 256>>>(w_qkv, w_proj);
    split_x_kernel<<<(8 * 128 * 4096) / 256, 256>>>(x);

    // 1) qkv = w_qkv @ x   (M=768, Kp=128)
    gemm_kernel<<<dim3(HW / 128, 6, NB), 256, GEMM_SMEM>>>(
        wqb, wqs, xb, xs, qkv, 128, nullptr, nullptr, nullptr, nullptr);

    // 2) agg = grouped-pw(depthwise5x5(qkv))
    dwpw_kernel<<<dim3(4, 96, NB), 256>>>(qkv, w_dw, w_pw, agg);

    // 3) kv reduction per (b, head)
    kv_kernel<<<dim3(64, NB), 256>>>(qkv, agg, kv);

    // 4) apply -> att (fp16 split, fused)
    apply_kernel<<<dim3(HW / 256, 64, NB), 256>>>(qkv, agg, kv, attb, atts);

    // 5) out = BN(w_proj @ att)   (M=256, Kp=256)
    gemm_kernel<<<dim3(HW / 128, 2, NB), 256, GEMM_SMEM>>>(
        wpb, wps, attb, atts, out, 256, bn_gamma, bn_beta, bn_mean, bn_var);
}

// round 15
// speedup vs baseline: 1.3247x; 1.0158x over previous
#include <cuda_runtime.h>
#include <cuda_fp16.h>
#include <cstdint>

// ---------------- scratch (no allocations allowed) ----------------
__device__ float    g_qkv[(size_t)8 * 768 * 4096];   // fp32
__device__ float    g_agg[(size_t)8 * 768 * 4096];   // fp32
__device__ float    g_kv[8 * 64 * 72];
// packed half2 (k even, k odd) split operands
__device__ uint32_t g_xb[(size_t)8 * 128 * 4096];    // x big   [b][kp][px]
__device__ uint32_t g_xs[(size_t)8 * 128 * 4096];    // x small
__device__ uint32_t g_attb[(size_t)8 * 256 * 4096];  // att big [b][kp][px]
__device__ uint32_t g_atts[(size_t)8 * 256 * 4096];
__device__ uint32_t g_wqb[768 * 128];                // w_qkv big  [m][kp]
__device__ uint32_t g_wqs[768 * 128];
__device__ uint32_t g_wpb[256 * 256];                // w_proj big [m][kp]
__device__ uint32_t g_wps[256 * 256];

#define HW 4096
#define NB 8
#define A_SCALE 128.0f
#define B_SCALE 16.0f
#define INV_SC  (1.0f / (A_SCALE * B_SCALE))   // 2^-11

// split scaled pair into packed fp16 big + small
__device__ __forceinline__ void splith(float x, float y, float sc,
                                       uint32_t& pb, uint32_t& ps) {
    float xs = x * sc, ys = y * sc;
    __half hx = __float2half_rn(xs), hy = __float2half_rn(ys);
    float rx = xs - __half2float(hx), ry = ys - __half2float(hy);
    __half sx = __float2half_rn(rx), sy = __float2half_rn(ry);
    __half2 vb = __halves2half2(hx, hy);
    __half2 vs = __halves2half2(sx, sy);
    pb = *reinterpret_cast<uint32_t*>(&vb);
    ps = *reinterpret_cast<uint32_t*>(&vs);
}

#define MMA_F16(C, Ar, Br)                                               \
    asm volatile(                                                        \
        "mma.sync.aligned.m16n8k16.row.col.f32.f16.f16.f32 "             \
        "{%0,%1,%2,%3}, {%4,%5,%6,%7}, {%8,%9}, {%0,%1,%2,%3};"          \
        : "+f"((C)[0]), "+f"((C)[1]), "+f"((C)[2]), "+f"((C)[3])         \
        : "r"((Ar)[0]), "r"((Ar)[1]), "r"((Ar)[2]), "r"((Ar)[3]),        \
          "r"((Br)[0]), "r"((Br)[1]))

#define CP_ASYNC16(smem_addr, gptr)                                      \
    asm volatile("cp.async.cg.shared.global [%0], [%1], 16;"             \
                 :: "r"(smem_addr), "l"(gptr) : "memory")

// ---------------- weight split kernel (tiny) ----------------
__global__ void split_w_kernel(const float* __restrict__ wq,
                               const float* __restrict__ wp)
{
    int idx = blockIdx.x * 256 + threadIdx.x;
    if (idx < 768 * 128) {
        int m = idx >> 7, kp = idx & 127;
        float2 v = *reinterpret_cast<const float2*>(&wq[m * 256 + 2 * kp]);
        splith(v.x, v.y, A_SCALE, g_wqb[idx], g_wqs[idx]);
    } else {
        int j = idx - 768 * 128;
        if (j < 256 * 256) {
            int m = j >> 8, kp = j & 255;
            float2 v = *reinterpret_cast<const float2*>(&wp[m * 512 + 2 * kp]);
            splith(v.x, v.y, A_SCALE, g_wpb[j], g_wps[j]);
        }
    }
}

// ---------------- x split kernel ----------------
__global__ __launch_bounds__(256)
void split_x_kernel(const float* __restrict__ x)
{
    int idx = blockIdx.x * 256 + threadIdx.x;    // [b][kp][p]
    int p = idx & 4095;
    int rest = idx >> 12;
    int kp = rest & 127;
    int b = rest >> 7;
    const float* xp = x + ((size_t)b * 256 + 2 * kp) * HW + p;
    splith(xp[0], xp[HW], B_SCALE, g_xb[idx], g_xs[idx]);
}

// ---------------- fp16 split tensor-core GEMM, cp.async 3-stage pipeline ----------------
// Grid: (m-tiles, n-tiles, batch) — m fastest so CTAs sharing a B tile are
// co-resident and B is served from L2 after one DRAM read.
#define ST_AS 10240
#define ST_BB 20480
#define ST_BS 29184
#define STAGE 37888
#define GEMM_SMEM (3 * STAGE)   // 113664

__global__ __launch_bounds__(256, 2)
void gemm_kernel(const uint32_t* __restrict__ Ab, const uint32_t* __restrict__ As,
                 const uint32_t* __restrict__ Bb, const uint32_t* __restrict__ Bs,
                 float* __restrict__ Cdst, int Kp,
                 const float* __restrict__ bn_gamma, const float* __restrict__ bn_beta,
                 const float* __restrict__ bn_mean,  const float* __restrict__ bn_var)
{
    extern __shared__ __align__(16) char smem[];
    uint32_t sbase;
    asm("{ .reg .u64 t; cvta.to.shared.u64 t, %1; cvt.u32.u64 %0, t; }"
        : "=r"(sbase) : "l"(smem));

    const int tid  = threadIdx.x;
    const int lane = tid & 31;
    const int warp = tid >> 5;
    const int warpM = (warp >> 2) * 64;
    const int warpN = (warp & 3) * 32;
    const int lq = lane >> 2;
    const int lr = lane & 3;

    const int b  = blockIdx.z;
    const int m0 = blockIdx.x * 128;   // m fastest -> B-tile sharers adjacent
    const int n0 = blockIdx.y * 128;
    const int M  = gridDim.x * 128;
    const uint32_t* Bpb = Bb + (size_t)b * Kp * HW;
    const uint32_t* Bps = Bs + (size_t)b * Kp * HW;
    float* Cp = Cdst + (size_t)b * M * HW;

    const int arow = tid >> 2, aq = (tid & 3) * 4;
    const int arow2 = (tid + 256) >> 2, aq2 = ((tid + 256) & 3) * 4;
    const int brow = tid >> 5, bcg = (tid & 31) * 4;
    const int brow2 = (tid + 256) >> 5, bcg2 = ((tid + 256) & 31) * 4;

    float c[4][4][4];
#pragma unroll
    for (int mi = 0; mi < 4; mi++)
#pragma unroll
        for (int ni = 0; ni < 4; ni++)
#pragma unroll
            for (int r = 0; r < 4; r++) c[mi][ni][r] = 0.f;

    const int nch = Kp >> 4;

    auto load_stage = [&](int st, int ck) {
        uint32_t sb = sbase + st * STAGE;
        const uint32_t* a0 = Ab + (size_t)(m0 + arow) * Kp + ck * 16 + aq;
        const uint32_t* a1 = Ab + (size_t)(m0 + arow2) * Kp + ck * 16 + aq2;
        const uint32_t* a2 = As + (size_t)(m0 + arow) * Kp + ck * 16 + aq;
        const uint32_t* a3 = As + (size_t)(m0 + arow2) * Kp + ck * 16 + aq2;
        CP_ASYNC16(sb + (arow * 20 + aq) * 4, a0);
        CP_ASYNC16(sb + (arow2 * 20 + aq2) * 4, a1);
        CP_ASYNC16(sb + ST_AS + (arow * 20 + aq) * 4, a2);
        CP_ASYNC16(sb + ST_AS + (arow2 * 20 + aq2) * 4, a3);
        const uint32_t* b0 = Bpb + (size_t)(ck * 16 + brow) * HW + n0 + bcg;
        const uint32_t* b1 = Bpb + (size_t)(ck * 16 + brow2) * HW + n0 + bcg2;
        const uint32_t* b2 = Bps + (size_t)(ck * 16 + brow) * HW + n0 + bcg;
        const uint32_t* b3 = Bps + (size_t)(ck * 16 + brow2) * HW + n0 + bcg2;
        CP_ASYNC16(sb + ST_BB + (brow * 136 + bcg) * 4, b0);
        CP_ASYNC16(sb + ST_BB + (brow2 * 136 + bcg2) * 4, b1);
        CP_ASYNC16(sb + ST_BS + (brow * 136 + bcg) * 4, b2);
        CP_ASYNC16(sb + ST_BS + (brow2 * 136 + bcg2) * 4, b3);
        asm volatile("cp.async.commit_group;" ::: "memory");
    };

    // prologue: stages 0 and 1 in flight
    load_stage(0, 0);
    load_stage(1, 1);

    int st = 0;                      // stage of chunk ck
    for (int ck = 0; ck < nch; ++ck) {
        if (ck + 1 < nch) {
            asm volatile("cp.async.wait_group 1;" ::: "memory");
        } else {
            asm volatile("cp.async.wait_group 0;" ::: "memory");
        }
        __syncthreads();
        if (ck + 2 < nch) {
            int st2 = st + 2 >= 3 ? st - 1 : st + 2;
            load_stage(st2, ck + 2);
        }

        const uint32_t* Ab_s = (const uint32_t*)(smem + st * STAGE);
        const uint32_t* As_s = (const uint32_t*)(smem + st * STAGE + ST_AS);
        const uint32_t* Bb_s = (const uint32_t*)(smem + st * STAGE + ST_BB);
        const uint32_t* Bs_s = (const uint32_t*)(smem + st * STAGE + ST_BS);

#pragma unroll
        for (int ks = 0; ks < 2; ++ks) {
            const int kb = ks * 8;
            uint32_t bbf[4][2], bsf[4][2];
#pragma unroll
            for (int ni = 0; ni < 4; ++ni) {
                int col = warpN + ni * 8 + lq;
                bbf[ni][0] = Bb_s[(kb + lr) * 136 + col];
                bbf[ni][1] = Bb_s[(kb + lr + 4) * 136 + col];
                bsf[ni][0] = Bs_s[(kb + lr) * 136 + col];
                bsf[ni][1] = Bs_s[(kb + lr + 4) * 136 + col];
            }
#pragma unroll
            for (int mi = 0; mi < 4; ++mi) {
                int r = warpM + mi * 16 + lq;
                int kc = kb + lr;
                uint32_t abf[4] = { Ab_s[r * 20 + kc], Ab_s[(r + 8) * 20 + kc],
                                    Ab_s[r * 20 + kc + 4], Ab_s[(r + 8) * 20 + kc + 4] };
                uint32_t asf[4] = { As_s[r * 20 + kc], As_s[(r + 8) * 20 + kc],
                                    As_s[r * 20 + kc + 4], As_s[(r + 8) * 20 + kc + 4] };
#pragma unroll
                for (int ni = 0; ni < 4; ++ni) {
                    MMA_F16(c[mi][ni], asf, bbf[ni]);   // small x big
                    MMA_F16(c[mi][ni], abf, bsf[ni]);   // big x small
                    MMA_F16(c[mi][ni], abf, bbf[ni]);   // big x big
                }
            }
        }
        st = (st + 1 == 3) ? 0 : st + 1;
    }

#pragma unroll
    for (int mi = 0; mi < 4; ++mi) {
        int r0 = m0 + warpM + mi * 16 + lq;
        int r1 = r0 + 8;
        float s0 = INV_SC, b0 = 0.f, s1 = INV_SC, b1 = 0.f;
        if (bn_gamma) {
            float inv0 = bn_gamma[r0] * rsqrtf(bn_var[r0] + 1e-5f);
            float inv1 = bn_gamma[r1] * rsqrtf(bn_var[r1] + 1e-5f);
            s0 = inv0 * INV_SC; b0 = bn_beta[r0] - bn_mean[r0] * inv0;
            s1 = inv1 * INV_SC; b1 = bn_beta[r1] - bn_mean[r1] * inv1;
        }
#pragma unroll
        for (int ni = 0; ni < 4; ++ni) {
            int n = n0 + warpN + ni * 8 + lr * 2;
            float2 v0, v1;
            v0.x = c[mi][ni][0] * s0 + b0;
            v0.y = c[mi][ni][1] * s0 + b0;
            v1.x = c[mi][ni][2] * s1 + b1;
            v1.y = c[mi][ni][3] * s1 + b1;
            *reinterpret_cast<float2*>(&Cp[(size_t)r0 * HW + n]) = v0;
            *reinterpret_cast<float2*>(&Cp[(size_t)r1 * HW + n]) = v1;
        }
    }
}

// ---------------- fused depthwise 5x5 + grouped pointwise 8x8 -> agg ----------------
// EXACT R11 version (measured 134us). Do not perturb.
__global__ __launch_bounds__(256, 2)
void dwpw_kernel(const float* __restrict__ qkv,
                 const float* __restrict__ w_dw,
                 const float* __restrict__ w_pw,
                 float* __restrict__ agg)
{
    const int tile = blockIdx.x;
    const int g = blockIdx.y;
    const int b = blockIdx.z;
    const int ty0 = (tile >> 1) * 32;
    const int tx0 = (tile & 1) * 32;

    __shared__ float s_in[8][36][36];
    __shared__ float s_dw[8][25];
    __shared__ float s_pw[8][8];

    const int tid = threadIdx.x;
    if (tid < 200) s_dw[tid / 25][tid % 25] = w_dw[(g * 8 + tid / 25) * 25 + tid % 25];
    if (tid < 64)  s_pw[tid >> 3][tid & 7] = w_pw[g * 64 + tid];

    const float* base = qkv + ((size_t)b * 768 + g * 8) * HW;
    for (int idx = tid; idx < 8 * 36 * 36; idx += 256) {
        int c = idx / 1296;
        int rem = idx - c * 1296;
        int r = rem / 36;
        int col = rem - r * 36;
        int y = ty0 + r - 2, x = tx0 + col - 2;
        float v = 0.f;
        if (y >= 0 && y < 64 && x >= 0 && x < 64) v = base[(size_t)c * HW + y * 64 + x];
        s_in[c][r][col] = v;
    }
    __syncthreads();

    const int px  = tid & 31;       // column within tile
    const int py0 = (tid >> 5) * 4; // strip of 4 output rows

    float out[8][4];
#pragma unroll
    for (int o = 0; o < 8; ++o)
#pragma unroll
        for (int p = 0; p < 4; ++p) out[o][p] = 0.f;

#pragma unroll
    for (int c = 0; c < 8; ++c) {
        float w[25];
#pragma unroll
        for (int i = 0; i < 25; ++i) w[i] = s_dw[c][i];

        float acc[4] = {0.f, 0.f, 0.f, 0.f};
#pragma unroll
        for (int j = 0; j < 8; ++j) {
            float win[5];
#pragma unroll
            for (int dx = 0; dx < 5; ++dx) win[dx] = s_in[c][py0 + j][px + dx];
#pragma unroll
            for (int o = 0; o < 4; ++o) {
                const int dy = j - o;
                if (dy >= 0 && dy <= 4) {
#pragma unroll
                    for (int dx = 0; dx < 5; ++dx)
                        acc[o] = fmaf(win[dx], w[dy * 5 + dx], acc[o]);
                }
            }
        }
#pragma unroll
        for (int o = 0; o < 8; ++o) {
            float pw = s_pw[o][c];
#pragma unroll
            for (int p = 0; p < 4; ++p) out[o][p] = fmaf(pw, acc[p], out[o][p]);
        }
    }

    float* obase = agg + ((size_t)b * 768 + g * 8) * HW;
#pragma unroll
    for (int o = 0; o < 8; ++o) {
#pragma unroll
        for (int p = 0; p < 4; ++p) {
            int off = (ty0 + py0 + p) * 64 + (tx0 + px);
            obase[(size_t)o * HW + off] = out[o][p];
        }
    }
}

// ---------------- kv = sum_p relu(k)_d * [v_e | 1]  per (b, head) ----------------
__global__ __launch_bounds__(256, 4)
void kv_kernel(const float* __restrict__ qkv,
               const float* __restrict__ agg,
               float* __restrict__ kvout)
{
    const int h = blockIdx.x, b = blockIdx.y;
    const float* src = (h < 32) ? qkv : agg;
    const int cbase = (h & 31) * 24;
    const float* kp = src + ((size_t)b * 768 + cbase + 8) * HW;
    const float* vp = src + ((size_t)b * 768 + cbase + 16) * HW;

    float acc[8][9];
#pragma unroll
    for (int d = 0; d < 8; d++)
#pragma unroll
        for (int e = 0; e < 9; e++) acc[d][e] = 0.f;

    for (int p = threadIdx.x; p < HW; p += 256) {
        float kk[8], vv[8];
#pragma unroll
        for (int d = 0; d < 8; d++) kk[d] = fmaxf(kp[(size_t)d * HW + p], 0.f);
#pragma unroll
        for (int e = 0; e < 8; e++) vv[e] = vp[(size_t)e * HW + p];
#pragma unroll
        for (int d = 0; d < 8; d++) {
#pragma unroll
            for (int e = 0; e < 8; e++) acc[d][e] = fmaf(kk[d], vv[e], acc[d][e]);
            acc[d][8] += kk[d];
        }
    }

    __shared__ float red[8][72];
    const int lane = threadIdx.x & 31, w = threadIdx.x >> 5;
#pragma unroll
    for (int i = 0; i < 72; ++i) {
        float v = acc[i / 9][i % 9];
#pragma unroll
        for (int off = 16; off; off >>= 1) v += __shfl_down_sync(0xffffffffu, v, off);
        if (lane == 0) red[w][i] = v;
    }
    __syncthreads();
    if (threadIdx.x < 72) {
        float s = 0.f;
#pragma unroll
        for (int w2 = 0; w2 < 8; ++w2) s += red[w2][threadIdx.x];
        kvout[((size_t)b * 64 + h) * 72 + threadIdx.x] = s;
    }
}

// ---------------- apply + fused att split, 4 pixels/thread (float4 I/O) ----------------
__global__ __launch_bounds__(256, 4)
void apply_kernel(const float* __restrict__ qkv,
                  const float* __restrict__ agg,
                  const float* __restrict__ kvin,
                  uint32_t* __restrict__ attb,
                  uint32_t* __restrict__ atts)
{
    const int h = blockIdx.y, b = blockIdx.z;
    __shared__ float kv[8][9];
    if (threadIdx.x < 72)
        kv[threadIdx.x / 9][threadIdx.x % 9] = kvin[((size_t)b * 64 + h) * 72 + threadIdx.x];
    __syncthreads();

    const float* src = (h < 32) ? qkv : agg;
    const int cbase = (h & 31) * 24;
    const float* qp = src + ((size_t)b * 768 + cbase) * HW;
    const int p = (blockIdx.x * 256 + threadIdx.x) * 4;

    float4 q[8];
#pragma unroll
    for (int d = 0; d < 8; d++) {
        float4 v = *reinterpret_cast<const float4*>(&qp[(size_t)d * HW + p]);
        v.x = fmaxf(v.x, 0.f); v.y = fmaxf(v.y, 0.f);
        v.z = fmaxf(v.z, 0.f); v.w = fmaxf(v.w, 0.f);
        q[d] = v;
    }

    float4 den = make_float4(0.f, 0.f, 0.f, 0.f);
#pragma unroll
    for (int d = 0; d < 8; d++) {
        float kd = kv[d][8];
        den.x = fmaf(q[d].x, kd, den.x);
        den.y = fmaf(q[d].y, kd, den.y);
        den.z = fmaf(q[d].z, kd, den.z);
        den.w = fmaf(q[d].w, kd, den.w);
    }
    float4 inv;
    inv.x = 1.f / (den.x + 1e-15f);
    inv.y = 1.f / (den.y + 1e-15f);
    inv.z = 1.f / (den.z + 1e-15f);
    inv.w = 1.f / (den.w + 1e-15f);

    float o[8][4];
#pragma unroll
    for (int n = 0; n < 8; ++n) {
        float4 s = make_float4(0.f, 0.f, 0.f, 0.f);
#pragma unroll
        for (int d = 0; d < 8; d++) {
            float kn = kv[d][n];
            s.x = fmaf(q[d].x, kn, s.x);
            s.y = fmaf(q[d].y, kn, s.y);
            s.z = fmaf(q[d].z, kn, s.z);
            s.w = fmaf(q[d].w, kn, s.w);
        }
        o[n][0] = s.x * inv.x; o[n][1] = s.y * inv.y;
        o[n][2] = s.z * inv.z; o[n][3] = s.w * inv.w;
    }

    uint32_t* wb = attb + ((size_t)b * 256 + h * 4) * HW + p;
    uint32_t* ws = atts + ((size_t)b * 256 + h * 4) * HW + p;
#pragma unroll
    for (int j = 0; j < 4; ++j) {
        uint4 vb4, vs4;
        splith(o[2 * j][0], o[2 * j + 1][0], B_SCALE, vb4.x, vs4.x);
        splith(o[2 * j][1], o[2 * j + 1][1], B_SCALE, vb4.y, vs4.y);
        splith(o[2 * j][2], o[2 * j + 1][2], B_SCALE, vb4.z, vs4.z);
        splith(o[2 * j][3], o[2 * j + 1][3], B_SCALE, vb4.w, vs4.w);
        *reinterpret_cast<uint4*>(&wb[(size_t)j * HW]) = vb4;
        *reinterpret_cast<uint4*>(&ws[(size_t)j * HW]) = vs4;
    }
}

// ---------------- launch ----------------
extern "C" void kernel_launch(void* const* d_in, const int* in_sizes, int n_in,
                              void* d_out, int out_size)
{
    const float* x        = (const float*)d_in[0];
    const float* w_qkv    = (const float*)d_in[1];
    const float* w_dw     = (const float*)d_in[2];
    const float* w_pw     = (const float*)d_in[3];
    const float* w_proj   = (const float*)d_in[4];
    const float* bn_gamma = (const float*)d_in[5];
    const float* bn_beta  = (const float*)d_in[6];
    const float* bn_mean  = (const float*)d_in[7];
    const float* bn_var   = (const float*)d_in[8];
    float* out = (float*)d_out;

    float *qkv, *agg, *kv;
    uint32_t *xb, *xs, *attb, *atts, *wqb, *wqs, *wpb, *wps;
    cudaGetSymbolAddress((void**)&qkv,  g_qkv);
    cudaGetSymbolAddress((void**)&agg,  g_agg);
    cudaGetSymbolAddress((void**)&kv,   g_kv);
    cudaGetSymbolAddress((void**)&xb,   g_xb);
    cudaGetSymbolAddress((void**)&xs,   g_xs);
    cudaGetSymbolAddress((void**)&attb, g_attb);
    cudaGetSymbolAddress((void**)&atts, g_atts);
    cudaGetSymbolAddress((void**)&wqb,  g_wqb);
    cudaGetSymbolAddress((void**)&wqs,  g_wqs);
    cudaGetSymbolAddress((void**)&wpb,  g_wpb);
    cudaGetSymbolAddress((void**)&wps,  g_wps);

    cudaFuncSetAttribute(gemm_kernel,
                         cudaFuncAttributeMaxDynamicSharedMemorySize, GEMM_SMEM);

    // 0) pre-split weights and x into fp16 big/small (packed pairs)
    split_w_kernel<<<(768 * 128 + 256 * 256 + 255) / 256, 256>>>(w_qkv, w_proj);
    split_x_kernel<<<(8 * 128 * 4096) / 256, 256>>>(x);

    // 1) qkv = w_qkv @ x   (M=768, Kp=128); m-tiles fastest for B L2 reuse
    gemm_kernel<<<dim3(6, HW / 128, NB), 256, GEMM_SMEM>>>(
        wqb, wqs, xb, xs, qkv, 128, nullptr, nullptr, nullptr, nullptr);

    // 2) agg = grouped-pw(depthwise5x5(qkv))
    dwpw_kernel<<<dim3(4, 96, NB), 256>>>(qkv, w_dw, w_pw, agg);

    // 3) kv reduction per (b, head)
    kv_kernel<<<dim3(64, NB), 256>>>(qkv, agg, kv);

    // 4) apply -> att (fp16 split, fused), 4 px/thread
    apply_kernel<<<dim3(HW / 1024, 64, NB), 256>>>(qkv, agg, kv, attb, atts);

    // 5) out = BN(w_proj @ att)   (M=256, Kp=256); m-tiles fastest
    gemm_kernel<<<dim3(2, HW / 128, NB), 256, GEMM_SMEM>>>(
        wpb, wps, attb, atts, out, 256, bn_gamma, bn_beta, bn_mean, bn_var);
}

// round 16
// speedup vs baseline: 1.3373x; 1.0095x over previous
#include <cuda_runtime.h>
#include <cuda_fp16.h>
#include <cstdint>

// ---------------- scratch (no allocations allowed) ----------------
__device__ float    g_qkv[(size_t)8 * 768 * 4096];   // fp32
__device__ float    g_agg[(size_t)8 * 768 * 4096];   // fp32
__device__ float    g_kv[8 * 64 * 72];
// packed half2 (k even, k odd) split operands
__device__ uint32_t g_xb[(size_t)8 * 128 * 4096];    // x big   [b][kp][px]
__device__ uint32_t g_xs[(size_t)8 * 128 * 4096];    // x small
__device__ uint32_t g_attb[(size_t)8 * 256 * 4096];  // att big [b][kp][px]
__device__ uint32_t g_atts[(size_t)8 * 256 * 4096];
__device__ uint32_t g_wqb[768 * 128];                // w_qkv big  [m][kp]
__device__ uint32_t g_wqs[768 * 128];
__device__ uint32_t g_wpb[256 * 256];                // w_proj big [m][kp]
__device__ uint32_t g_wps[256 * 256];

#define HW 4096
#define NB 8
#define A_SCALE 128.0f
#define B_SCALE 16.0f
#define INV_SC  (1.0f / (A_SCALE * B_SCALE))   // 2^-11

// split scaled pair into packed fp16 big + small
__device__ __forceinline__ void splith(float x, float y, float sc,
                                       uint32_t& pb, uint32_t& ps) {
    float xs = x * sc, ys = y * sc;
    __half hx = __float2half_rn(xs), hy = __float2half_rn(ys);
    float rx = xs - __half2float(hx), ry = ys - __half2float(hy);
    __half sx = __float2half_rn(rx), sy = __float2half_rn(ry);
    __half2 vb = __halves2half2(hx, hy);
    __half2 vs = __halves2half2(sx, sy);
    pb = *reinterpret_cast<uint32_t*>(&vb);
    ps = *reinterpret_cast<uint32_t*>(&vs);
}

#define MMA_F16(C, Ar, Br)                                               \
    asm volatile(                                                        \
        "mma.sync.aligned.m16n8k16.row.col.f32.f16.f16.f32 "             \
        "{%0,%1,%2,%3}, {%4,%5,%6,%7}, {%8,%9}, {%0,%1,%2,%3};"          \
        : "+f"((C)[0]), "+f"((C)[1]), "+f"((C)[2]), "+f"((C)[3])         \
        : "r"((Ar)[0]), "r"((Ar)[1]), "r"((Ar)[2]), "r"((Ar)[3]),        \
          "r"((Br)[0]), "r"((Br)[1]))

#define CP_ASYNC16(smem_addr, gptr)                                      \
    asm volatile("cp.async.cg.shared.global [%0], [%1], 16;"             \
                 :: "r"(smem_addr), "l"(gptr) : "memory")

// ---------------- weight split kernel (tiny) ----------------
__global__ void split_w_kernel(const float* __restrict__ wq,
                               const float* __restrict__ wp)
{
    int idx = blockIdx.x * 256 + threadIdx.x;
    if (idx < 768 * 128) {
        int m = idx >> 7, kp = idx & 127;
        float2 v = *reinterpret_cast<const float2*>(&wq[m * 256 + 2 * kp]);
        splith(v.x, v.y, A_SCALE, g_wqb[idx], g_wqs[idx]);
    } else {
        int j = idx - 768 * 128;
        if (j < 256 * 256) {
            int m = j >> 8, kp = j & 255;
            float2 v = *reinterpret_cast<const float2*>(&wp[m * 512 + 2 * kp]);
            splith(v.x, v.y, A_SCALE, g_wpb[j], g_wps[j]);
        }
    }
}

// ---------------- x split kernel ----------------
__global__ __launch_bounds__(256)
void split_x_kernel(const float* __restrict__ x)
{
    int idx = blockIdx.x * 256 + threadIdx.x;    // [b][kp][p]
    int p = idx & 4095;
    int rest = idx >> 12;
    int kp = rest & 127;
    int b = rest >> 7;
    const float* xp = x + ((size_t)b * 256 + 2 * kp) * HW + p;
    splith(xp[0], xp[HW], B_SCALE, g_xb[idx], g_xs[idx]);
}

// ---------------- fp16 split tensor-core GEMM, cp.async 3-stage pipeline ----------------
#define ST_AS 10240
#define ST_BB 20480
#define ST_BS 29184
#define STAGE 37888
#define GEMM_SMEM (3 * STAGE)   // 113664

__global__ __launch_bounds__(256, 2)
void gemm_kernel(const uint32_t* __restrict__ Ab, const uint32_t* __restrict__ As,
                 const uint32_t* __restrict__ Bb, const uint32_t* __restrict__ Bs,
                 float* __restrict__ Cdst, int Kp,
                 const float* __restrict__ bn_gamma, const float* __restrict__ bn_beta,
                 const float* __restrict__ bn_mean,  const float* __restrict__ bn_var)
{
    extern __shared__ __align__(16) char smem[];
    uint32_t sbase;
    asm("{ .reg .u64 t; cvta.to.shared.u64 t, %1; cvt.u32.u64 %0, t; }"
        : "=r"(sbase) : "l"(smem));

    const int tid  = threadIdx.x;
    const int lane = tid & 31;
    const int warp = tid >> 5;
    const int warpM = (warp >> 2) * 64;
    const int warpN = (warp & 3) * 32;
    const int lq = lane >> 2;
    const int lr = lane & 3;

    const int b  = blockIdx.z;
    const int m0 = blockIdx.x * 128;   // m fastest -> B-tile sharers adjacent
    const int n0 = blockIdx.y * 128;
    const int M  = gridDim.x * 128;
    const uint32_t* Bpb = Bb + (size_t)b * Kp * HW;
    const uint32_t* Bps = Bs + (size_t)b * Kp * HW;
    float* Cp = Cdst + (size_t)b * M * HW;

    const int arow = tid >> 2, aq = (tid & 3) * 4;
    const int arow2 = (tid + 256) >> 2, aq2 = ((tid + 256) & 3) * 4;
    const int brow = tid >> 5, bcg = (tid & 31) * 4;
    const int brow2 = (tid + 256) >> 5, bcg2 = ((tid + 256) & 31) * 4;

    float c[4][4][4];
#pragma unroll
    for (int mi = 0; mi < 4; mi++)
#pragma unroll
        for (int ni = 0; ni < 4; ni++)
#pragma unroll
            for (int r = 0; r < 4; r++) c[mi][ni][r] = 0.f;

    const int nch = Kp >> 4;

    auto load_stage = [&](int st, int ck) {
        uint32_t sb = sbase + st * STAGE;
        const uint32_t* a0 = Ab + (size_t)(m0 + arow) * Kp + ck * 16 + aq;
        const uint32_t* a1 = Ab + (size_t)(m0 + arow2) * Kp + ck * 16 + aq2;
        const uint32_t* a2 = As + (size_t)(m0 + arow) * Kp + ck * 16 + aq;
        const uint32_t* a3 = As + (size_t)(m0 + arow2) * Kp + ck * 16 + aq2;
        CP_ASYNC16(sb + (arow * 20 + aq) * 4, a0);
        CP_ASYNC16(sb + (arow2 * 20 + aq2) * 4, a1);
        CP_ASYNC16(sb + ST_AS + (arow * 20 + aq) * 4, a2);
        CP_ASYNC16(sb + ST_AS + (arow2 * 20 + aq2) * 4, a3);
        const uint32_t* b0 = Bpb + (size_t)(ck * 16 + brow) * HW + n0 + bcg;
        const uint32_t* b1 = Bpb + (size_t)(ck * 16 + brow2) * HW + n0 + bcg2;
        const uint32_t* b2 = Bps + (size_t)(ck * 16 + brow) * HW + n0 + bcg;
        const uint32_t* b3 = Bps + (size_t)(ck * 16 + brow2) * HW + n0 + bcg2;
        CP_ASYNC16(sb + ST_BB + (brow * 136 + bcg) * 4, b0);
        CP_ASYNC16(sb + ST_BB + (brow2 * 136 + bcg2) * 4, b1);
        CP_ASYNC16(sb + ST_BS + (brow * 136 + bcg) * 4, b2);
        CP_ASYNC16(sb + ST_BS + (brow2 * 136 + bcg2) * 4, b3);
        asm volatile("cp.async.commit_group;" ::: "memory");
    };

    // prologue: stages 0 and 1 in flight
    load_stage(0, 0);
    load_stage(1, 1);

    int st = 0;                      // stage of chunk ck
    for (int ck = 0; ck < nch; ++ck) {
        if (ck + 1 < nch) {
            asm volatile("cp.async.wait_group 1;" ::: "memory");
        } else {
            asm volatile("cp.async.wait_group 0;" ::: "memory");
        }
        __syncthreads();
        if (ck + 2 < nch) {
            int st2 = st + 2 >= 3 ? st - 1 : st + 2;
            load_stage(st2, ck + 2);
        }

        const uint32_t* Ab_s = (const uint32_t*)(smem + st * STAGE);
        const uint32_t* As_s = (const uint32_t*)(smem + st * STAGE + ST_AS);
        const uint32_t* Bb_s = (const uint32_t*)(smem + st * STAGE + ST_BB);
        const uint32_t* Bs_s = (const uint32_t*)(smem + st * STAGE + ST_BS);

#pragma unroll
        for (int ks = 0; ks < 2; ++ks) {
            const int kb = ks * 8;
            uint32_t bbf[4][2], bsf[4][2];
#pragma unroll
            for (int ni = 0; ni < 4; ++ni) {
                int col = warpN + ni * 8 + lq;
                bbf[ni][0] = Bb_s[(kb + lr) * 136 + col];
                bbf[ni][1] = Bb_s[(kb + lr + 4) * 136 + col];
                bsf[ni][0] = Bs_s[(kb + lr) * 136 + col];
                bsf[ni][1] = Bs_s[(kb + lr + 4) * 136 + col];
            }
#pragma unroll
            for (int mi = 0; mi < 4; ++mi) {
                int r = warpM + mi * 16 + lq;
                int kc = kb + lr;
                uint32_t abf[4] = { Ab_s[r * 20 + kc], Ab_s[(r + 8) * 20 + kc],
                                    Ab_s[r * 20 + kc + 4], Ab_s[(r + 8) * 20 + kc + 4] };
                uint32_t asf[4] = { As_s[r * 20 + kc], As_s[(r + 8) * 20 + kc],
                                    As_s[r * 20 + kc + 4], As_s[(r + 8) * 20 + kc + 4] };
#pragma unroll
                for (int ni = 0; ni < 4; ++ni) {
                    MMA_F16(c[mi][ni], asf, bbf[ni]);   // small x big
                    MMA_F16(c[mi][ni], abf, bsf[ni]);   // big x small
                    MMA_F16(c[mi][ni], abf, bbf[ni]);   // big x big
                }
            }
        }
        st = (st + 1 == 3) ? 0 : st + 1;
    }

#pragma unroll
    for (int mi = 0; mi < 4; ++mi) {
        int r0 = m0 + warpM + mi * 16 + lq;
        int r1 = r0 + 8;
        float s0 = INV_SC, b0 = 0.f, s1 = INV_SC, b1 = 0.f;
        if (bn_gamma) {
            float inv0 = bn_gamma[r0] * rsqrtf(bn_var[r0] + 1e-5f);
            float inv1 = bn_gamma[r1] * rsqrtf(bn_var[r1] + 1e-5f);
            s0 = inv0 * INV_SC; b0 = bn_beta[r0] - bn_mean[r0] * inv0;
            s1 = inv1 * INV_SC; b1 = bn_beta[r1] - bn_mean[r1] * inv1;
        }
#pragma unroll
        for (int ni = 0; ni < 4; ++ni) {
            int n = n0 + warpN + ni * 8 + lr * 2;
            float2 v0, v1;
            v0.x = c[mi][ni][0] * s0 + b0;
            v0.y = c[mi][ni][1] * s0 + b0;
            v1.x = c[mi][ni][2] * s1 + b1;
            v1.y = c[mi][ni][3] * s1 + b1;
            *reinterpret_cast<float2*>(&Cp[(size_t)r0 * HW + n]) = v0;
            *reinterpret_cast<float2*>(&Cp[(size_t)r1 * HW + n]) = v1;
        }
    }
}

// ---------------- fused depthwise 5x5 + grouped pointwise 8x8 -> agg ----------------
// R11 compute loop (measured-fast, unmodified). Loader keeps the SAME strided
// loop shape but replaces div/mod with carry counters (256 = 7*36 + 4) and
// uses the flat smem store address (== idx).
__global__ __launch_bounds__(256, 2)
void dwpw_kernel(const float* __restrict__ qkv,
                 const float* __restrict__ w_dw,
                 const float* __restrict__ w_pw,
                 float* __restrict__ agg)
{
    const int tile = blockIdx.x;
    const int g = blockIdx.y;
    const int b = blockIdx.z;
    const int ty0 = (tile >> 1) * 32;
    const int tx0 = (tile & 1) * 32;

    __shared__ float s_in[8][36][36];
    __shared__ float s_dw[8][25];
    __shared__ float s_pw[8][8];

    const int tid = threadIdx.x;
    if (tid < 200) s_dw[tid / 25][tid % 25] = w_dw[(g * 8 + tid / 25) * 25 + tid % 25];
    if (tid < 64)  s_pw[tid >> 3][tid & 7] = w_pw[g * 64 + tid];

    const float* base = qkv + ((size_t)b * 768 + g * 8) * HW;
    {
        float* s_flat = &s_in[0][0][0];
        const int yoff = ty0 - 2, xoff = tx0 - 2;
        int cc = 0;
        int r = tid / 36;            // one division, once (tid < 256 -> cc = 0)
        int col = tid - r * 36;
        for (int idx = tid; idx < 8 * 36 * 36; idx += 256) {
            int y = yoff + r, x = xoff + col;
            float v = 0.f;
            if ((unsigned)y < 64u && (unsigned)x < 64u)
                v = base[(cc << 12) + (y << 6) + x];
            s_flat[idx] = v;
            // advance by 256 = 7*36 + 4
            col += 4; r += 7;
            if (col >= 36) { col -= 36; r += 1; }
            if (r >= 36)   { r -= 36; cc += 1; }
        }
    }
    __syncthreads();

    const int px  = tid & 31;       // column within tile
    const int py0 = (tid >> 5) * 4; // strip of 4 output rows

    float out[8][4];
#pragma unroll
    for (int o = 0; o < 8; ++o)
#pragma unroll
        for (int p = 0; p < 4; ++p) out[o][p] = 0.f;

#pragma unroll
    for (int c = 0; c < 8; ++c) {
        float w[25];
#pragma unroll
        for (int i = 0; i < 25; ++i) w[i] = s_dw[c][i];

        float acc[4] = {0.f, 0.f, 0.f, 0.f};
#pragma unroll
        for (int j = 0; j < 8; ++j) {
            float win[5];
#pragma unroll
            for (int dx = 0; dx < 5; ++dx) win[dx] = s_in[c][py0 + j][px + dx];
#pragma unroll
            for (int o = 0; o < 4; ++o) {
                const int dy = j - o;
                if (dy >= 0 && dy <= 4) {
#pragma unroll
                    for (int dx = 0; dx < 5; ++dx)
                        acc[o] = fmaf(win[dx], w[dy * 5 + dx], acc[o]);
                }
            }
        }
#pragma unroll
        for (int o = 0; o < 8; ++o) {
            float pw = s_pw[o][c];
#pragma unroll
            for (int p = 0; p < 4; ++p) out[o][p] = fmaf(pw, acc[p], out[o][p]);
        }
    }

    float* obase = agg + ((size_t)b * 768 + g * 8) * HW;
#pragma unroll
    for (int o = 0; o < 8; ++o) {
#pragma unroll
        for (int p = 0; p < 4; ++p) {
            int off = (ty0 + py0 + p) * 64 + (tx0 + px);
            obase[(size_t)o * HW + off] = out[o][p];
        }
    }
}

// ---------------- kv = sum_p relu(k)_d * [v_e | 1]  per (b, head) ----------------
__global__ __launch_bounds__(256, 4)
void kv_kernel(const float* __restrict__ qkv,
               const float* __restrict__ agg,
               float* __restrict__ kvout)
{
    const int h = blockIdx.x, b = blockIdx.y;
    const float* src = (h < 32) ? qkv : agg;
    const int cbase = (h & 31) * 24;
    const float* kp = src + ((size_t)b * 768 + cbase + 8) * HW;
    const float* vp = src + ((size_t)b * 768 + cbase + 16) * HW;

    float acc[8][9];
#pragma unroll
    for (int d = 0; d < 8; d++)
#pragma unroll
        for (int e = 0; e < 9; e++) acc[d][e] = 0.f;

    for (int p = threadIdx.x; p < HW; p += 256) {
        float kk[8], vv[8];
#pragma unroll
        for (int d = 0; d < 8; d++) kk[d] = fmaxf(kp[(size_t)d * HW + p], 0.f);
#pragma unroll
        for (int e = 0; e < 8; e++) vv[e] = vp[(size_t)e * HW + p];
#pragma unroll
        for (int d = 0; d < 8; d++) {
#pragma unroll
            for (int e = 0; e < 8; e++) acc[d][e] = fmaf(kk[d], vv[e], acc[d][e]);
            acc[d][8] += kk[d];
        }
    }

    __shared__ float red[8][72];
    const int lane = threadIdx.x & 31, w = threadIdx.x >> 5;
#pragma unroll
    for (int i = 0; i < 72; ++i) {
        float v = acc[i / 9][i % 9];
#pragma unroll
        for (int off = 16; off; off >>= 1) v += __shfl_down_sync(0xffffffffu, v, off);
        if (lane == 0) red[w][i] = v;
    }
    __syncthreads();
    if (threadIdx.x < 72) {
        float s = 0.f;
#pragma unroll
        for (int w2 = 0; w2 < 8; ++w2) s += red[w2][threadIdx.x];
        kvout[((size_t)b * 64 + h) * 72 + threadIdx.x] = s;
    }
}

// ---------------- apply + fused att split, 4 pixels/thread (float4 I/O) ----------------
__global__ __launch_bounds__(256, 4)
void apply_kernel(const float* __restrict__ qkv,
                  const float* __restrict__ agg,
                  const float* __restrict__ kvin,
                  uint32_t* __restrict__ attb,
                  uint32_t* __restrict__ atts)
{
    const int h = blockIdx.y, b = blockIdx.z;
    __shared__ float kv[8][9];
    if (threadIdx.x < 72)
        kv[threadIdx.x / 9][threadIdx.x % 9] = kvin[((size_t)b * 64 + h) * 72 + threadIdx.x];
    __syncthreads();

    const float* src = (h < 32) ? qkv : agg;
    const int cbase = (h & 31) * 24;
    const float* qp = src + ((size_t)b * 768 + cbase) * HW;
    const int p = (blockIdx.x * 256 + threadIdx.x) * 4;

    float4 q[8];
#pragma unroll
    for (int d = 0; d < 8; d++) {
        float4 v = *reinterpret_cast<const float4*>(&qp[(size_t)d * HW + p]);
        v.x = fmaxf(v.x, 0.f); v.y = fmaxf(v.y, 0.f);
        v.z = fmaxf(v.z, 0.f); v.w = fmaxf(v.w, 0.f);
        q[d] = v;
    }

    float4 den = make_float4(0.f, 0.f, 0.f, 0.f);
#pragma unroll
    for (int d = 0; d < 8; d++) {
        float kd = kv[d][8];
        den.x = fmaf(q[d].x, kd, den.x);
        den.y = fmaf(q[d].y, kd, den.y);
        den.z = fmaf(q[d].z, kd, den.z);
        den.w = fmaf(q[d].w, kd, den.w);
    }
    float4 inv;
    inv.x = 1.f / (den.x + 1e-15f);
    inv.y = 1.f / (den.y + 1e-15f);
    inv.z = 1.f / (den.z + 1e-15f);
    inv.w = 1.f / (den.w + 1e-15f);

    float o[8][4];
#pragma unroll
    for (int n = 0; n < 8; ++n) {
        float4 s = make_float4(0.f, 0.f, 0.f, 0.f);
#pragma unroll
        for (int d = 0; d < 8; d++) {
            float kn = kv[d][n];
            s.x = fmaf(q[d].x, kn, s.x);
            s.y = fmaf(q[d].y, kn, s.y);
            s.z = fmaf(q[d].z, kn, s.z);
            s.w = fmaf(q[d].w, kn, s.w);
        }
        o[n][0] = s.x * inv.x; o[n][1] = s.y * inv.y;
        o[n][2] = s.z * inv.z; o[n][3] = s.w * inv.w;
    }

    uint32_t* wb = attb + ((size_t)b * 256 + h * 4) * HW + p;
    uint32_t* ws = atts + ((size_t)b * 256 + h * 4) * HW + p;
#pragma unroll
    for (int j = 0; j < 4; ++j) {
        uint4 vb4, vs4;
        splith(o[2 * j][0], o[2 * j + 1][0], B_SCALE, vb4.x, vs4.x);
        splith(o[2 * j][1], o[2 * j + 1][1], B_SCALE, vb4.y, vs4.y);
        splith(o[2 * j][2], o[2 * j + 1][2], B_SCALE, vb4.z, vs4.z);
        splith(o[2 * j][3], o[2 * j + 1][3], B_SCALE, vb4.w, vs4.w);
        *reinterpret_cast<uint4*>(&wb[(size_t)j * HW]) = vb4;
        *reinterpret_cast<uint4*>(&ws[(size_t)j * HW]) = vs4;
    }
}

// ---------------- launch ----------------
extern "C" void kernel_launch(void* const* d_in, const int* in_sizes, int n_in,
                              void* d_out, int out_size)
{
    const float* x        = (const float*)d_in[0];
    const float* w_qkv    = (const float*)d_in[1];
    const float* w_dw     = (const float*)d_in[2];
    const float* w_pw     = (const float*)d_in[3];
    const float* w_proj   = (const float*)d_in[4];
    const float* bn_gamma = (const float*)d_in[5];
    const float* bn_beta  = (const float*)d_in[6];
    const float* bn_mean  = (const float*)d_in[7];
    const float* bn_var   = (const float*)d_in[8];
    float* out = (float*)d_out;

    float *qkv, *agg, *kv;
    uint32_t *xb, *xs, *attb, *atts, *wqb, *wqs, *wpb, *wps;
    cudaGetSymbolAddress((void**)&qkv,  g_qkv);
    cudaGetSymbolAddress((void**)&agg,  g_agg);
    cudaGetSymbolAddress((void**)&kv,   g_kv);
    cudaGetSymbolAddress((void**)&xb,   g_xb);
    cudaGetSymbolAddress((void**)&xs,   g_xs);
    cudaGetSymbolAddress((void**)&attb, g_attb);
    cudaGetSymbolAddress((void**)&atts, g_atts);
    cudaGetSymbolAddress((void**)&wqb,  g_wqb);
    cudaGetSymbolAddress((void**)&wqs,  g_wqs);
    cudaGetSymbolAddress((void**)&wpb,  g_wpb);
    cudaGetSymbolAddress((void**)&wps,  g_wps);

    cudaFuncSetAttribute(gemm_kernel,
                         cudaFuncAttributeMaxDynamicSharedMemorySize, GEMM_SMEM);

    // 0) pre-split weights and x into fp16 big/small (packed pairs)
    split_w_kernel<<<(768 * 128 + 256 * 256 + 255) / 256, 256>>>(w_qkv, w_proj);
    split_x_kernel<<<(8 * 128 * 4096) / 256, 256>>>(x);

    // 1) qkv = w_qkv @ x   (M=768, Kp=128); m-tiles fastest for B L2 reuse
    gemm_kernel<<<dim3(6, HW / 128, NB), 256, GEMM_SMEM>>>(
        wqb, wqs, xb, xs, qkv, 128, nullptr, nullptr, nullptr, nullptr);

    // 2) agg = grouped-pw(depthwise5x5(qkv))
    dwpw_kernel<<<dim3(4, 96, NB), 256>>>(qkv, w_dw, w_pw, agg);

    // 3) kv reduction per (b, head)
    kv_kernel<<<dim3(64, NB), 256>>>(qkv, agg, kv);

    // 4) apply -> att (fp16 split, fused), 4 px/thread
    apply_kernel<<<dim3(HW / 1024, 64, NB), 256>>>(qkv, agg, kv, attb, atts);

    // 5) out = BN(w_proj @ att)   (M=256, Kp=256); m-tiles fastest
    gemm_kernel<<<dim3(2, HW / 128, NB), 256, GEMM_SMEM>>>(
        wpb, wps, attb, atts, out, 256, bn_gamma, bn_beta, bn_mean, bn_var);
}